// round 15
// baseline (speedup 1.0000x reference)
#include <cuda_runtime.h>
#include <math.h>

#define Bx 32
#define Tx 128
#define Hx 256
#define Mx 1000
#define Qx 4
#define TILE_M 8
#define NTILES 125   // 1000 / 8

// ------------------------- device scratch -------------------------
__device__ float gH [Bx*Tx*Hx];            // h = (x@proj_w + b) * valid
__device__ float gHC[Bx*Tx*8];             // conv-block output
__device__ float gE [Bx*Tx];
__device__ float gS [Bx*Tx];
__device__ int   gML[Bx];
__device__ float gY [(size_t)Bx*Qx*Tx*Hx]; // Y[b,q,t,o]  (16 MB)

// ------------------------- kDur -------------------------
__global__ void kDur(const float* __restrict__ xdur, float* __restrict__ outLens) {
    int b = blockIdx.x;
    if (threadIdx.x == 0) {
        float run = 0.f;
        for (int t = 0; t < Tx; t++) {
            float d = xdur[b*Tx + t];
            gS[b*Tx + t] = run;
            run += d;
            gE[b*Tx + t] = run;
        }
        int ml = (int)rintf(run);
        if (ml > Mx) ml = Mx;
        gML[b] = ml;
        outLens[b] = (float)ml;
    }
}

// ------------------------- kHY: fused x@proj_w (seg 0) and x@proj1_w_q (segs 1-4) -----
// grid (Bx, 8 row-tiles of 16, 5 segs), 128 threads = 1280 blocks.
// rg = tid>>5 owns 4 rows, oc = (tid&31)*8 owns 8 cols. acc 32 regs.
__global__ void __launch_bounds__(128) kHY(const float* __restrict__ x,
                                           const float* __restrict__ proj_w,
                                           const float* __restrict__ proj_b,
                                           const float* __restrict__ p1w,
                                           const int*   __restrict__ xlens) {
    __shared__ float xs[16][Hx];   // 16KB
    int b   = blockIdx.x;
    int t0  = blockIdx.y * 16;
    int seg = blockIdx.z;
    int tid = threadIdx.x;

    {
        const float4* src = reinterpret_cast<const float4*>(x + (size_t)(b*Tx + t0)*Hx);
        float4* dst = reinterpret_cast<float4*>(&xs[0][0]);
        #pragma unroll
        for (int i = 0; i < 8; i++)
            dst[tid + i*128] = src[tid + i*128];
    }
    __syncthreads();

    const float* W = (seg == 0) ? proj_w : (p1w + (size_t)(seg-1)*Hx*Hx);
    int rg = tid >> 5;            // 0..3
    int oc = (tid & 31) << 3;     // 0..248
    int r0 = rg << 2;             // 4 rows per thread

    float acc[4][8];
    #pragma unroll
    for (int i = 0; i < 4; i++)
        #pragma unroll
        for (int j = 0; j < 8; j++) acc[i][j] = 0.f;

    #pragma unroll 2
    for (int h = 0; h < Hx; h++) {
        float4 wa = *reinterpret_cast<const float4*>(W + (size_t)h*Hx + oc);
        float4 wb = *reinterpret_cast<const float4*>(W + (size_t)h*Hx + oc + 4);
        #pragma unroll
        for (int i = 0; i < 4; i++) {
            float xv = xs[r0 + i][h];
            acc[i][0] = fmaf(xv, wa.x, acc[i][0]);
            acc[i][1] = fmaf(xv, wa.y, acc[i][1]);
            acc[i][2] = fmaf(xv, wa.z, acc[i][2]);
            acc[i][3] = fmaf(xv, wa.w, acc[i][3]);
            acc[i][4] = fmaf(xv, wb.x, acc[i][4]);
            acc[i][5] = fmaf(xv, wb.y, acc[i][5]);
            acc[i][6] = fmaf(xv, wb.z, acc[i][6]);
            acc[i][7] = fmaf(xv, wb.w, acc[i][7]);
        }
    }

    if (seg == 0) {
        int xlen = xlens[b];
        float4 pba = *reinterpret_cast<const float4*>(proj_b + oc);
        float4 pbb = *reinterpret_cast<const float4*>(proj_b + oc + 4);
        #pragma unroll
        for (int i = 0; i < 4; i++) {
            int row = t0 + r0 + i;
            float4 o1, o2;
            o1.x = acc[i][0]+pba.x; o1.y = acc[i][1]+pba.y; o1.z = acc[i][2]+pba.z; o1.w = acc[i][3]+pba.w;
            o2.x = acc[i][4]+pbb.x; o2.y = acc[i][5]+pbb.y; o2.z = acc[i][6]+pbb.z; o2.w = acc[i][7]+pbb.w;
            if (row >= xlen) { o1 = make_float4(0,0,0,0); o2 = make_float4(0,0,0,0); }
            float* dst = &gH[(size_t)(b*Tx + row)*Hx + oc];
            *reinterpret_cast<float4*>(dst)     = o1;
            *reinterpret_cast<float4*>(dst + 4) = o2;
        }
    } else {
        int q = seg - 1;
        #pragma unroll
        for (int i = 0; i < 4; i++) {
            int row = t0 + r0 + i;
            float* dst = &gY[(size_t)((b*Qx + q)*Tx + row)*Hx + oc];
            *reinterpret_cast<float4*>(dst)     = make_float4(acc[i][0], acc[i][1], acc[i][2], acc[i][3]);
            *reinterpret_cast<float4*>(dst + 4) = make_float4(acc[i][4], acc[i][5], acc[i][6], acc[i][7]);
        }
    }
}

// ------------------------- kConv: conv1d(k=3) + LN(8) + silu, *valid -------------------------
__global__ void __launch_bounds__(Hx) kConv(const float* __restrict__ cw,
                                            const float* __restrict__ cb,
                                            const float* __restrict__ cg,
                                            const float* __restrict__ cbeta,
                                            const int*   __restrict__ xlens) {
    int bt = blockIdx.x;
    int b = bt >> 7, t = bt & 127;
    int cin = threadIdx.x;

    float hm = (t > 0)   ? gH[(size_t)(bt-1)*Hx + cin] : 0.f;
    float h0 =             gH[(size_t) bt   *Hx + cin];
    float hp = (t < 127) ? gH[(size_t)(bt+1)*Hx + cin] : 0.f;

    float loc[8];
    #pragma unroll
    for (int c = 0; c < 8; c++) {
        const float* w = cw + c*(Hx*3) + cin*3;
        loc[c] = fmaf(w[0], hm, fmaf(w[1], h0, w[2]*hp));
    }
    #pragma unroll
    for (int off = 16; off > 0; off >>= 1) {
        #pragma unroll
        for (int c = 0; c < 8; c++)
            loc[c] += __shfl_xor_sync(0xffffffffu, loc[c], off);
    }
    __shared__ float red[8][8];
    __shared__ float tmp8[8];
    int warp = cin >> 5, lane = cin & 31;
    if (lane == 0) {
        #pragma unroll
        for (int c = 0; c < 8; c++) red[warp][c] = loc[c];
    }
    __syncthreads();
    if (cin < 8) {
        float v = cb[cin];
        #pragma unroll
        for (int w = 0; w < 8; w++) v += red[w][cin];
        tmp8[cin] = v;
    }
    __syncthreads();
    if (cin < 8) {
        float mu = 0.f;
        #pragma unroll
        for (int j = 0; j < 8; j++) mu += tmp8[j];
        mu *= 0.125f;
        float var = 0.f;
        #pragma unroll
        for (int j = 0; j < 8; j++) { float d = tmp8[j]-mu; var = fmaf(d, d, var); }
        var *= 0.125f;
        float zn = (tmp8[cin]-mu) * rsqrtf(var + 1e-5f) * cg[cin] + cbeta[cin];
        float sil = zn / (1.f + expf(-zn));
        gHC[bt*8 + cin] = (t < xlens[b]) ? sil : 0.f;
    }
}

// ------------------------- kMain: 128 threads, reg-capped for 8 blocks/SM (R8) -------------------------
__global__ void __launch_bounds__(128, 8) kMain(
    const int*   __restrict__ xlens,
    const float* __restrict__ qw1, const float* __restrict__ qb1,
    const float* __restrict__ qg,  const float* __restrict__ qbeta,
    const float* __restrict__ qw2, const float* __restrict__ qb2,
    const float* __restrict__ pw1, const float* __restrict__ pb1,
    const float* __restrict__ pg,  const float* __restrict__ pbeta,
    const float* __restrict__ pw2, const float* __restrict__ pb2,
    const float* __restrict__ p1b, const float* __restrict__ p2w,
    const float* __restrict__ p2b, const float* __restrict__ pow_,
    const float* __restrict__ pob,
    float* __restrict__ outO, float* __restrict__ outMask,
    float* __restrict__ outW)
{
    __shared__ float w_sh[TILE_M][Tx][4];   // 16KB; u_sh aliases front 8KB after phase 2
    __shared__ float wc_sh[TILE_M][8];
    __shared__ float redM[2][4][12];        // parity double-buffered merged reduction

    int b    = blockIdx.x % Bx;
    int tile = blockIdx.x / Bx;
    int m0   = tile * TILE_M;
    int t    = threadIdx.x;
    int warp = t >> 5, lane = t & 31;
    int mel_len = gML[b];
    int xlen    = xlens[b];

    // -------- fully padded tile fast path --------
    if (m0 >= mel_len) {
        int j4 = t << 2;
        float4 pb4 = *reinterpret_cast<const float4*>(pob + j4);
        #pragma unroll
        for (int mi = 0; mi < TILE_M; mi++) {
            int m = m0 + mi;
            outMask[(size_t)(b*Mx + m)*Tx + t] = 1.f;
            #pragma unroll
            for (int q = 0; q < 4; q++)
                outW[((size_t)(b*Qx + q)*Mx + m)*Tx + t] = 0.f;
            *reinterpret_cast<float4*>(outO + (size_t)(b*Mx + m)*(2*Hx) + j4) = pb4;
        }
        return;
    }

    bool tmask = (t >= xlen);
    float fh[8];
    #pragma unroll
    for (int c = 0; c < 8; c++) fh[c] = gHC[(b*Tx + t)*8 + c];
    float se = gE[b*Tx + t], ss = gS[b*Tx + t];

    // m-independent parts of the two tiny MLPs
    float zqb[4];
    #pragma unroll
    for (int q = 0; q < 4; q++) zqb[q] = qb1[q];
    #pragma unroll
    for (int i = 0; i < 8; i++) {
        #pragma unroll
        for (int q = 0; q < 4; q++) zqb[q] = fmaf(fh[i], qw1[i*4 + q], zqb[q]);
    }
    float zpb0 = pb1[0], zpb1 = pb1[1];
    #pragma unroll
    for (int i = 0; i < 8; i++) {
        zpb0 = fmaf(fh[i], pw1[i*2 + 0], zpb0);
        zpb1 = fmaf(fh[i], pw1[i*2 + 1], zpb1);
    }

    // -------- phase 1: per-m scores, softmax (no max-sub), merged wc reduce --------
    for (int mi = 0; mi < TILE_M; mi++) {
        int m = m0 + mi;
        bool pad = (m >= mel_len);          // block-uniform
        outMask[(size_t)(b*Mx + m)*Tx + t] = pad ? 1.f : 0.f;
        if (pad) {
            #pragma unroll
            for (int q = 0; q < 4; q++) {
                w_sh[mi][t][q] = 0.f;
                outW[((size_t)(b*Qx + q)*Mx + m)*Tx + t] = 0.f;
            }
            if (t < 8) wc_sh[mi][t] = 0.f;
            continue;                       // pad is a suffix: no later redM writes
        }
        float tf = (float)(m + 1);
        float f8 = tmask ? 0.f : (tf - ss);
        float f9 = tmask ? 0.f : (se - tf);

        // q-MLP
        float z[4];
        #pragma unroll
        for (int q = 0; q < 4; q++)
            z[q] = fmaf(f9, qw1[36 + q], fmaf(f8, qw1[32 + q], zqb[q]));
        float mu = 0.25f * (z[0] + z[1] + z[2] + z[3]);
        float var = 0.f;
        #pragma unroll
        for (int q = 0; q < 4; q++) { float d = z[q]-mu; var = fmaf(d, d, var); }
        var *= 0.25f;
        float rinv = rsqrtf(var + 1e-5f);
        float a[4];
        #pragma unroll
        for (int q = 0; q < 4; q++) {
            float zn = (z[q]-mu) * rinv * qg[q] + qbeta[q];
            a[q] = __fdividef(zn, 1.f + __expf(-zn));
        }
        float ex[4];
        #pragma unroll
        for (int q = 0; q < 4; q++) {
            float s = qb2[q];
            #pragma unroll
            for (int j = 0; j < 4; j++) s = fmaf(a[j], qw2[j*4 + q], s);
            ex[q] = tmask ? 0.f : __expf(s);
        }

        // p-MLP
        float zp0 = fmaf(f9, pw1[18], fmaf(f8, pw1[16], zpb0));
        float zp1 = fmaf(f9, pw1[19], fmaf(f8, pw1[17], zpb1));
        float mup  = 0.5f * (zp0 + zp1);
        float d0 = zp0 - mup, d1 = zp1 - mup;
        float varp = 0.5f * (d0*d0 + d1*d1);
        float rp = rsqrtf(varp + 1e-5f);
        float a0 = d0 * rp * pg[0] + pbeta[0];
        float a1 = d1 * rp * pg[1] + pbeta[1];
        a0 = __fdividef(a0, 1.f + __expf(-a0));
        a1 = __fdividef(a1, 1.f + __expf(-a1));
        float c0 = fmaf(a1, pw2[2], fmaf(a0, pw2[0], pb2[0]));
        float c1 = fmaf(a1, pw2[3], fmaf(a0, pw2[1], pb2[1]));

        // merged 12-wide reduction: [ex0..ex3, ex_q*c_p (q-major)]
        float vv[12];
        #pragma unroll
        for (int q = 0; q < 4; q++) {
            vv[q]       = ex[q];
            vv[4 + q*2]     = ex[q]*c0;
            vv[4 + q*2 + 1] = ex[q]*c1;
        }
        #pragma unroll
        for (int off = 16; off > 0; off >>= 1) {
            #pragma unroll
            for (int k = 0; k < 12; k++)
                vv[k] += __shfl_xor_sync(0xffffffffu, vv[k], off);
        }
        int pbuf = mi & 1;
        if (lane == 0) {
            #pragma unroll
            for (int k = 0; k < 12; k++) redM[pbuf][warp][k] = vv[k];
        }
        __syncthreads();
        float sum[4];
        #pragma unroll
        for (int q = 0; q < 4; q++)
            sum[q] = redM[pbuf][0][q] + redM[pbuf][1][q] + redM[pbuf][2][q] + redM[pbuf][3][q];
        #pragma unroll
        for (int q = 0; q < 4; q++) {
            float wgt = __fdividef(ex[q], sum[q]);
            w_sh[mi][t][q] = wgt;
            outW[((size_t)(b*Qx + q)*Mx + m)*Tx + t] = wgt;
        }
        if (t < 8) {
            float num = redM[pbuf][0][4+t] + redM[pbuf][1][4+t]
                      + redM[pbuf][2][4+t] + redM[pbuf][3][4+t];
            wc_sh[mi][t] = __fdividef(num, sum[t >> 1]);
        }
    }
    __syncthreads();

    // -------- phase 2: wh accumulate (thread owns 8 m x 2 adjacent o) --------
    int o2 = t << 1;   // 0..254
    float acc0[TILE_M], acc1[TILE_M];
    #pragma unroll
    for (int mi = 0; mi < TILE_M; mi++) { acc0[mi] = 0.f; acc1[mi] = 0.f; }

    const float* yb = gY + (size_t)b*Qx*Tx*Hx + o2;
    #pragma unroll 2
    for (int tt = 0; tt < xlen; tt++) {
        float2 y0 = *reinterpret_cast<const float2*>(yb + ((size_t)(0*Tx + tt) << 8));
        float2 y1 = *reinterpret_cast<const float2*>(yb + ((size_t)(1*Tx + tt) << 8));
        float2 y2 = *reinterpret_cast<const float2*>(yb + ((size_t)(2*Tx + tt) << 8));
        float2 y3 = *reinterpret_cast<const float2*>(yb + ((size_t)(3*Tx + tt) << 8));
        #pragma unroll
        for (int mi = 0; mi < TILE_M; mi++) {
            float4 wv = *reinterpret_cast<const float4*>(&w_sh[mi][tt][0]);
            acc0[mi] = fmaf(wv.x, y0.x, acc0[mi]);
            acc1[mi] = fmaf(wv.x, y0.y, acc1[mi]);
            acc0[mi] = fmaf(wv.y, y1.x, acc0[mi]);
            acc1[mi] = fmaf(wv.y, y1.y, acc1[mi]);
            acc0[mi] = fmaf(wv.z, y2.x, acc0[mi]);
            acc1[mi] = fmaf(wv.z, y2.y, acc1[mi]);
            acc0[mi] = fmaf(wv.w, y3.x, acc0[mi]);
            acc1[mi] = fmaf(wv.w, y3.y, acc1[mi]);
        }
    }
    __syncthreads();   // all w_sh reads done; pool reused as u_sh

    float (*u_sh)[Hx] = reinterpret_cast<float(*)[Hx]>(&w_sh[0][0][0]);   // 8KB alias

    // -------- phase 3: u = wh + proj1_b + wc@proj2_w + proj2_b --------
    {
        float2 b1 = *reinterpret_cast<const float2*>(p1b + o2);
        float2 b2 = *reinterpret_cast<const float2*>(p2b + o2);
        #pragma unroll
        for (int mi = 0; mi < TILE_M; mi++) {
            int m = m0 + mi;
            float u0 = 0.f, u1 = 0.f;
            if (m < mel_len) {
                u0 = acc0[mi] + b1.x + b2.x;
                u1 = acc1[mi] + b1.y + b2.y;
                #pragma unroll
                for (int j = 0; j < 8; j++) {
                    float wc = wc_sh[mi][j];
                    float2 pp = *reinterpret_cast<const float2*>(p2w + j*Hx + o2);
                    u0 = fmaf(wc, pp.x, u0);
                    u1 = fmaf(wc, pp.y, u1);
                }
            }
            u_sh[mi][o2]     = u0;
            u_sh[mi][o2 + 1] = u1;
        }
    }
    __syncthreads();

    // -------- phase 4: o = u @ projo_w + projo_b (float4 u, 4 h per step) ----
    int j4 = t << 2;   // 0..508
    float acc2[TILE_M][4];
    #pragma unroll
    for (int mi = 0; mi < TILE_M; mi++)
        #pragma unroll
        for (int r = 0; r < 4; r++) acc2[mi][r] = 0.f;

    for (int h = 0; h < Hx; h += 4) {
        float4 pw0 = *reinterpret_cast<const float4*>(pow_ + (size_t)(h+0)*(2*Hx) + j4);
        float4 pw1v = *reinterpret_cast<const float4*>(pow_ + (size_t)(h+1)*(2*Hx) + j4);
        float4 pw2v = *reinterpret_cast<const float4*>(pow_ + (size_t)(h+2)*(2*Hx) + j4);
        float4 pw3 = *reinterpret_cast<const float4*>(pow_ + (size_t)(h+3)*(2*Hx) + j4);
        #pragma unroll
        for (int mi = 0; mi < TILE_M; mi++) {
            float4 uv = *reinterpret_cast<const float4*>(&u_sh[mi][h]);
            acc2[mi][0] = fmaf(uv.x, pw0.x, acc2[mi][0]);
            acc2[mi][1] = fmaf(uv.x, pw0.y, acc2[mi][1]);
            acc2[mi][2] = fmaf(uv.x, pw0.z, acc2[mi][2]);
            acc2[mi][3] = fmaf(uv.x, pw0.w, acc2[mi][3]);
            acc2[mi][0] = fmaf(uv.y, pw1v.x, acc2[mi][0]);
            acc2[mi][1] = fmaf(uv.y, pw1v.y, acc2[mi][1]);
            acc2[mi][2] = fmaf(uv.y, pw1v.z, acc2[mi][2]);
            acc2[mi][3] = fmaf(uv.y, pw1v.w, acc2[mi][3]);
            acc2[mi][0] = fmaf(uv.z, pw2v.x, acc2[mi][0]);
            acc2[mi][1] = fmaf(uv.z, pw2v.y, acc2[mi][1]);
            acc2[mi][2] = fmaf(uv.z, pw2v.z, acc2[mi][2]);
            acc2[mi][3] = fmaf(uv.z, pw2v.w, acc2[mi][3]);
            acc2[mi][0] = fmaf(uv.w, pw3.x, acc2[mi][0]);
            acc2[mi][1] = fmaf(uv.w, pw3.y, acc2[mi][1]);
            acc2[mi][2] = fmaf(uv.w, pw3.z, acc2[mi][2]);
            acc2[mi][3] = fmaf(uv.w, pw3.w, acc2[mi][3]);
        }
    }
    float4 pb4 = *reinterpret_cast<const float4*>(pob + j4);
    #pragma unroll
    for (int mi = 0; mi < TILE_M; mi++) {
        int m = m0 + mi;
        float4 ov;
        ov.x = acc2[mi][0] + pb4.x;
        ov.y = acc2[mi][1] + pb4.y;
        ov.z = acc2[mi][2] + pb4.z;
        ov.w = acc2[mi][3] + pb4.w;
        *reinterpret_cast<float4*>(outO + (size_t)(b*Mx + m)*(2*Hx) + j4) = ov;
    }
}

// ------------------------- launch -------------------------
extern "C" void kernel_launch(void* const* d_in, const int* in_sizes, int n_in,
                              void* d_out, int out_size) {
    (void)in_sizes; (void)n_in; (void)out_size;
    const float* x        = (const float*)d_in[0];
    const float* xdur     = (const float*)d_in[2];
    const int*   xlens    = (const int*)  d_in[3];
    const float* proj_w   = (const float*)d_in[4];
    const float* proj_b   = (const float*)d_in[5];
    const float* conv_w   = (const float*)d_in[6];
    const float* conv_b   = (const float*)d_in[7];
    const float* conv_g   = (const float*)d_in[8];
    const float* conv_bt  = (const float*)d_in[9];
    const float* q_w1     = (const float*)d_in[10];
    const float* q_b1     = (const float*)d_in[11];
    const float* q_g      = (const float*)d_in[12];
    const float* q_bt     = (const float*)d_in[13];
    const float* q_w2     = (const float*)d_in[14];
    const float* q_b2     = (const float*)d_in[15];
    const float* p_w1     = (const float*)d_in[16];
    const float* p_b1     = (const float*)d_in[17];
    const float* p_g      = (const float*)d_in[18];
    const float* p_bt     = (const float*)d_in[19];
    const float* p_w2     = (const float*)d_in[20];
    const float* p_b2     = (const float*)d_in[21];
    const float* proj1_w  = (const float*)d_in[22];
    const float* proj1_b  = (const float*)d_in[23];
    const float* proj2_w  = (const float*)d_in[24];
    const float* proj2_b  = (const float*)d_in[25];
    const float* projo_w  = (const float*)d_in[26];
    const float* projo_b  = (const float*)d_in[27];

    float* out     = (float*)d_out;
    float* outO    = out;                                    // B*M*2H
    float* outMask = out + (size_t)Bx*Mx*2*Hx;               // B*M*T
    float* outLens = outMask + (size_t)Bx*Mx*Tx;             // B
    float* outW    = outLens + Bx;                           // B*Q*M*T

    kDur<<<Bx, 32>>>(xdur, outLens);
    dim3 ghy(Bx, 8, 5);
    kHY<<<ghy, 128>>>(x, proj_w, proj_b, proj1_w, xlens);
    kConv<<<Bx*Tx, Hx>>>(conv_w, conv_b, conv_g, conv_bt, xlens);
    kMain<<<Bx*NTILES, 128>>>(xlens,
        q_w1, q_b1, q_g, q_bt, q_w2, q_b2,
        p_w1, p_b1, p_g, p_bt, p_w2, p_b2,
        proj1_b, proj2_w, proj2_b, projo_w, projo_b,
        outO, outMask, outW);
}

// round 16
// speedup vs baseline: 1.0807x; 1.0807x over previous
#include <cuda_runtime.h>
#include <math.h>

#define Bx 32
#define Tx 128
#define Hx 256
#define Mx 1000
#define Qx 4
#define TILE_M 8
#define NTILES 125   // 1000 / 8

// ------------------------- device scratch -------------------------
__device__ float gH [Bx*Tx*Hx];            // h = (x@proj_w + b) * valid
__device__ float gHC[Bx*Tx*8];             // conv-block output
__device__ float gE [Bx*Tx];
__device__ float gS [Bx*Tx];
__device__ int   gML[Bx];
__device__ float gY [(size_t)Bx*Qx*Tx*Hx]; // Y[b,q,t,o]  (16 MB)

// ------------------------- kHY: fused x@proj_w (seg 0) and x@proj1_w_q (segs 1-4) -----
// 128 threads: rg = tid>>5 owns 8 rows, oc = (tid&31)*8 owns 8 cols. (R14 champion)
__global__ void __launch_bounds__(128) kHY(const float* __restrict__ x,
                                           const float* __restrict__ proj_w,
                                           const float* __restrict__ proj_b,
                                           const float* __restrict__ p1w,
                                           const int*   __restrict__ xlens) {
    __shared__ float xs[32][Hx];   // 32KB
    int b   = blockIdx.x;
    int t0  = blockIdx.y * 32;
    int seg = blockIdx.z;
    int tid = threadIdx.x;

    {
        const float4* src = reinterpret_cast<const float4*>(x + (size_t)(b*Tx + t0)*Hx);
        float4* dst = reinterpret_cast<float4*>(&xs[0][0]);
        #pragma unroll
        for (int i = 0; i < 16; i++)
            dst[tid + i*128] = src[tid + i*128];
    }
    __syncthreads();

    const float* W = (seg == 0) ? proj_w : (p1w + (size_t)(seg-1)*Hx*Hx);
    int rg = tid >> 5;            // 0..3
    int oc = (tid & 31) << 3;     // 0..248
    int r0 = rg << 3;

    float acc[8][8];
    #pragma unroll
    for (int i = 0; i < 8; i++)
        #pragma unroll
        for (int j = 0; j < 8; j++) acc[i][j] = 0.f;

    #pragma unroll 2
    for (int h = 0; h < Hx; h++) {
        float4 wa = *reinterpret_cast<const float4*>(W + (size_t)h*Hx + oc);
        float4 wb = *reinterpret_cast<const float4*>(W + (size_t)h*Hx + oc + 4);
        #pragma unroll
        for (int i = 0; i < 8; i++) {
            float xv = xs[r0 + i][h];
            acc[i][0] = fmaf(xv, wa.x, acc[i][0]);
            acc[i][1] = fmaf(xv, wa.y, acc[i][1]);
            acc[i][2] = fmaf(xv, wa.z, acc[i][2]);
            acc[i][3] = fmaf(xv, wa.w, acc[i][3]);
            acc[i][4] = fmaf(xv, wb.x, acc[i][4]);
            acc[i][5] = fmaf(xv, wb.y, acc[i][5]);
            acc[i][6] = fmaf(xv, wb.z, acc[i][6]);
            acc[i][7] = fmaf(xv, wb.w, acc[i][7]);
        }
    }

    if (seg == 0) {
        int xlen = xlens[b];
        float4 pba = *reinterpret_cast<const float4*>(proj_b + oc);
        float4 pbb = *reinterpret_cast<const float4*>(proj_b + oc + 4);
        #pragma unroll
        for (int i = 0; i < 8; i++) {
            int row = t0 + r0 + i;
            float4 o1, o2;
            o1.x = acc[i][0]+pba.x; o1.y = acc[i][1]+pba.y; o1.z = acc[i][2]+pba.z; o1.w = acc[i][3]+pba.w;
            o2.x = acc[i][4]+pbb.x; o2.y = acc[i][5]+pbb.y; o2.z = acc[i][6]+pbb.z; o2.w = acc[i][7]+pbb.w;
            if (row >= xlen) { o1 = make_float4(0,0,0,0); o2 = make_float4(0,0,0,0); }
            float* dst = &gH[(size_t)(b*Tx + row)*Hx + oc];
            *reinterpret_cast<float4*>(dst)     = o1;
            *reinterpret_cast<float4*>(dst + 4) = o2;
        }
    } else {
        int q = seg - 1;
        #pragma unroll
        for (int i = 0; i < 8; i++) {
            int row = t0 + r0 + i;
            float* dst = &gY[(size_t)((b*Qx + q)*Tx + row)*Hx + oc];
            *reinterpret_cast<float4*>(dst)     = make_float4(acc[i][0], acc[i][1], acc[i][2], acc[i][3]);
            *reinterpret_cast<float4*>(dst + 4) = make_float4(acc[i][4], acc[i][5], acc[i][6], acc[i][7]);
        }
    }
}

// ------------------------- kConv: conv1d(k=3) + LN(8) + silu, *valid; + folded kDur ------
__global__ void __launch_bounds__(Hx) kConv(const float* __restrict__ cw,
                                            const float* __restrict__ cb,
                                            const float* __restrict__ cg,
                                            const float* __restrict__ cbeta,
                                            const int*   __restrict__ xlens,
                                            const float* __restrict__ xdur,
                                            float* __restrict__ outLens) {
    int bt = blockIdx.x;
    int b = bt >> 7, t = bt & 127;
    int cin = threadIdx.x;

    // folded kDur: thread 0 of each b's first block computes cumsum + mel_len.
    // kMain (the only consumer of gE/gS/gML/outLens) runs after this kernel.
    if (t == 0 && cin == 0) {
        float run = 0.f;
        for (int tt = 0; tt < Tx; tt++) {
            float d = xdur[b*Tx + tt];
            gS[b*Tx + tt] = run;
            run += d;
            gE[b*Tx + tt] = run;
        }
        int ml = (int)rintf(run);
        if (ml > Mx) ml = Mx;
        gML[b] = ml;
        outLens[b] = (float)ml;
    }

    float hm = (t > 0)   ? gH[(size_t)(bt-1)*Hx + cin] : 0.f;
    float h0 =             gH[(size_t) bt   *Hx + cin];
    float hp = (t < 127) ? gH[(size_t)(bt+1)*Hx + cin] : 0.f;

    float loc[8];
    #pragma unroll
    for (int c = 0; c < 8; c++) {
        const float* w = cw + c*(Hx*3) + cin*3;
        loc[c] = fmaf(w[0], hm, fmaf(w[1], h0, w[2]*hp));
    }
    #pragma unroll
    for (int off = 16; off > 0; off >>= 1) {
        #pragma unroll
        for (int c = 0; c < 8; c++)
            loc[c] += __shfl_xor_sync(0xffffffffu, loc[c], off);
    }
    __shared__ float red[8][8];
    __shared__ float tmp8[8];
    int warp = cin >> 5, lane = cin & 31;
    if (lane == 0) {
        #pragma unroll
        for (int c = 0; c < 8; c++) red[warp][c] = loc[c];
    }
    __syncthreads();
    if (cin < 8) {
        float v = cb[cin];
        #pragma unroll
        for (int w = 0; w < 8; w++) v += red[w][cin];
        tmp8[cin] = v;
    }
    __syncthreads();
    if (cin < 8) {
        float mu = 0.f;
        #pragma unroll
        for (int j = 0; j < 8; j++) mu += tmp8[j];
        mu *= 0.125f;
        float var = 0.f;
        #pragma unroll
        for (int j = 0; j < 8; j++) { float d = tmp8[j]-mu; var = fmaf(d, d, var); }
        var *= 0.125f;
        float zn = (tmp8[cin]-mu) * rsqrtf(var + 1e-5f) * cg[cin] + cbeta[cin];
        float sil = zn / (1.f + expf(-zn));
        gHC[bt*8 + cin] = (t < xlens[b]) ? sil : 0.f;
    }
}

// ------------------------- kMain: 128 threads, reg-capped for 8 blocks/SM (R8) -------------------------
__global__ void __launch_bounds__(128, 8) kMain(
    const int*   __restrict__ xlens,
    const float* __restrict__ qw1, const float* __restrict__ qb1,
    const float* __restrict__ qg,  const float* __restrict__ qbeta,
    const float* __restrict__ qw2, const float* __restrict__ qb2,
    const float* __restrict__ pw1, const float* __restrict__ pb1,
    const float* __restrict__ pg,  const float* __restrict__ pbeta,
    const float* __restrict__ pw2, const float* __restrict__ pb2,
    const float* __restrict__ p1b, const float* __restrict__ p2w,
    const float* __restrict__ p2b, const float* __restrict__ pow_,
    const float* __restrict__ pob,
    float* __restrict__ outO, float* __restrict__ outMask,
    float* __restrict__ outW)
{
    __shared__ float w_sh[TILE_M][Tx][4];   // 16KB; u_sh aliases front 8KB after phase 2
    __shared__ float wc_sh[TILE_M][8];
    __shared__ float redM[2][4][12];        // parity double-buffered merged reduction

    int b    = blockIdx.x % Bx;
    int tile = blockIdx.x / Bx;
    int m0   = tile * TILE_M;
    int t    = threadIdx.x;
    int warp = t >> 5, lane = t & 31;
    int mel_len = gML[b];
    int xlen    = xlens[b];

    // -------- fully padded tile fast path --------
    if (m0 >= mel_len) {
        int j4 = t << 2;
        float4 pb4 = *reinterpret_cast<const float4*>(pob + j4);
        #pragma unroll
        for (int mi = 0; mi < TILE_M; mi++) {
            int m = m0 + mi;
            outMask[(size_t)(b*Mx + m)*Tx + t] = 1.f;
            #pragma unroll
            for (int q = 0; q < 4; q++)
                outW[((size_t)(b*Qx + q)*Mx + m)*Tx + t] = 0.f;
            *reinterpret_cast<float4*>(outO + (size_t)(b*Mx + m)*(2*Hx) + j4) = pb4;
        }
        return;
    }

    bool tmask = (t >= xlen);
    float fh[8];
    #pragma unroll
    for (int c = 0; c < 8; c++) fh[c] = gHC[(b*Tx + t)*8 + c];
    float se = gE[b*Tx + t], ss = gS[b*Tx + t];

    // m-independent parts of the two tiny MLPs
    float zqb[4];
    #pragma unroll
    for (int q = 0; q < 4; q++) zqb[q] = qb1[q];
    #pragma unroll
    for (int i = 0; i < 8; i++) {
        #pragma unroll
        for (int q = 0; q < 4; q++) zqb[q] = fmaf(fh[i], qw1[i*4 + q], zqb[q]);
    }
    float zpb0 = pb1[0], zpb1 = pb1[1];
    #pragma unroll
    for (int i = 0; i < 8; i++) {
        zpb0 = fmaf(fh[i], pw1[i*2 + 0], zpb0);
        zpb1 = fmaf(fh[i], pw1[i*2 + 1], zpb1);
    }

    // -------- phase 1: per-m scores, softmax (no max-sub), merged wc reduce --------
    for (int mi = 0; mi < TILE_M; mi++) {
        int m = m0 + mi;
        bool pad = (m >= mel_len);          // block-uniform
        outMask[(size_t)(b*Mx + m)*Tx + t] = pad ? 1.f : 0.f;
        if (pad) {
            #pragma unroll
            for (int q = 0; q < 4; q++) {
                w_sh[mi][t][q] = 0.f;
                outW[((size_t)(b*Qx + q)*Mx + m)*Tx + t] = 0.f;
            }
            if (t < 8) wc_sh[mi][t] = 0.f;
            continue;                       // pad is a suffix: no later redM writes
        }
        float tf = (float)(m + 1);
        float f8 = tmask ? 0.f : (tf - ss);
        float f9 = tmask ? 0.f : (se - tf);

        // q-MLP
        float z[4];
        #pragma unroll
        for (int q = 0; q < 4; q++)
            z[q] = fmaf(f9, qw1[36 + q], fmaf(f8, qw1[32 + q], zqb[q]));
        float mu = 0.25f * (z[0] + z[1] + z[2] + z[3]);
        float var = 0.f;
        #pragma unroll
        for (int q = 0; q < 4; q++) { float d = z[q]-mu; var = fmaf(d, d, var); }
        var *= 0.25f;
        float rinv = rsqrtf(var + 1e-5f);
        float a[4];
        #pragma unroll
        for (int q = 0; q < 4; q++) {
            float zn = (z[q]-mu) * rinv * qg[q] + qbeta[q];
            a[q] = __fdividef(zn, 1.f + __expf(-zn));
        }
        float ex[4];
        #pragma unroll
        for (int q = 0; q < 4; q++) {
            float s = qb2[q];
            #pragma unroll
            for (int j = 0; j < 4; j++) s = fmaf(a[j], qw2[j*4 + q], s);
            ex[q] = tmask ? 0.f : __expf(s);
        }

        // p-MLP
        float zp0 = fmaf(f9, pw1[18], fmaf(f8, pw1[16], zpb0));
        float zp1 = fmaf(f9, pw1[19], fmaf(f8, pw1[17], zpb1));
        float mup  = 0.5f * (zp0 + zp1);
        float d0 = zp0 - mup, d1 = zp1 - mup;
        float varp = 0.5f * (d0*d0 + d1*d1);
        float rp = rsqrtf(varp + 1e-5f);
        float a0 = d0 * rp * pg[0] + pbeta[0];
        float a1 = d1 * rp * pg[1] + pbeta[1];
        a0 = __fdividef(a0, 1.f + __expf(-a0));
        a1 = __fdividef(a1, 1.f + __expf(-a1));
        float c0 = fmaf(a1, pw2[2], fmaf(a0, pw2[0], pb2[0]));
        float c1 = fmaf(a1, pw2[3], fmaf(a0, pw2[1], pb2[1]));

        // merged 12-wide reduction: [ex0..ex3, ex_q*c_p (q-major)]
        float vv[12];
        #pragma unroll
        for (int q = 0; q < 4; q++) {
            vv[q]       = ex[q];
            vv[4 + q*2]     = ex[q]*c0;
            vv[4 + q*2 + 1] = ex[q]*c1;
        }
        #pragma unroll
        for (int off = 16; off > 0; off >>= 1) {
            #pragma unroll
            for (int k = 0; k < 12; k++)
                vv[k] += __shfl_xor_sync(0xffffffffu, vv[k], off);
        }
        int pbuf = mi & 1;
        if (lane == 0) {
            #pragma unroll
            for (int k = 0; k < 12; k++) redM[pbuf][warp][k] = vv[k];
        }
        __syncthreads();
        float sum[4];
        #pragma unroll
        for (int q = 0; q < 4; q++)
            sum[q] = redM[pbuf][0][q] + redM[pbuf][1][q] + redM[pbuf][2][q] + redM[pbuf][3][q];
        #pragma unroll
        for (int q = 0; q < 4; q++) {
            float wgt = __fdividef(ex[q], sum[q]);
            w_sh[mi][t][q] = wgt;
            outW[((size_t)(b*Qx + q)*Mx + m)*Tx + t] = wgt;
        }
        if (t < 8) {
            float num = redM[pbuf][0][4+t] + redM[pbuf][1][4+t]
                      + redM[pbuf][2][4+t] + redM[pbuf][3][4+t];
            wc_sh[mi][t] = __fdividef(num, sum[t >> 1]);
        }
    }
    __syncthreads();

    // -------- phase 2: wh accumulate (thread owns 8 m x 2 adjacent o) --------
    int o2 = t << 1;   // 0..254
    float acc0[TILE_M], acc1[TILE_M];
    #pragma unroll
    for (int mi = 0; mi < TILE_M; mi++) { acc0[mi] = 0.f; acc1[mi] = 0.f; }

    const float* yb = gY + (size_t)b*Qx*Tx*Hx + o2;
    #pragma unroll 2
    for (int tt = 0; tt < xlen; tt++) {
        float2 y0 = *reinterpret_cast<const float2*>(yb + ((size_t)(0*Tx + tt) << 8));
        float2 y1 = *reinterpret_cast<const float2*>(yb + ((size_t)(1*Tx + tt) << 8));
        float2 y2 = *reinterpret_cast<const float2*>(yb + ((size_t)(2*Tx + tt) << 8));
        float2 y3 = *reinterpret_cast<const float2*>(yb + ((size_t)(3*Tx + tt) << 8));
        #pragma unroll
        for (int mi = 0; mi < TILE_M; mi++) {
            float4 wv = *reinterpret_cast<const float4*>(&w_sh[mi][tt][0]);
            acc0[mi] = fmaf(wv.x, y0.x, acc0[mi]);
            acc1[mi] = fmaf(wv.x, y0.y, acc1[mi]);
            acc0[mi] = fmaf(wv.y, y1.x, acc0[mi]);
            acc1[mi] = fmaf(wv.y, y1.y, acc1[mi]);
            acc0[mi] = fmaf(wv.z, y2.x, acc0[mi]);
            acc1[mi] = fmaf(wv.z, y2.y, acc1[mi]);
            acc0[mi] = fmaf(wv.w, y3.x, acc0[mi]);
            acc1[mi] = fmaf(wv.w, y3.y, acc1[mi]);
        }
    }
    __syncthreads();   // all w_sh reads done; pool reused as u_sh

    float (*u_sh)[Hx] = reinterpret_cast<float(*)[Hx]>(&w_sh[0][0][0]);   // 8KB alias

    // -------- phase 3: u = wh + proj1_b + wc@proj2_w + proj2_b --------
    {
        float2 b1 = *reinterpret_cast<const float2*>(p1b + o2);
        float2 b2 = *reinterpret_cast<const float2*>(p2b + o2);
        #pragma unroll
        for (int mi = 0; mi < TILE_M; mi++) {
            int m = m0 + mi;
            float u0 = 0.f, u1 = 0.f;
            if (m < mel_len) {
                u0 = acc0[mi] + b1.x + b2.x;
                u1 = acc1[mi] + b1.y + b2.y;
                #pragma unroll
                for (int j = 0; j < 8; j++) {
                    float wc = wc_sh[mi][j];
                    float2 pp = *reinterpret_cast<const float2*>(p2w + j*Hx + o2);
                    u0 = fmaf(wc, pp.x, u0);
                    u1 = fmaf(wc, pp.y, u1);
                }
            }
            u_sh[mi][o2]     = u0;
            u_sh[mi][o2 + 1] = u1;
        }
    }
    __syncthreads();

    // -------- phase 4: o = u @ projo_w + projo_b (float4 u, 4 h per step) ----
    int j4 = t << 2;   // 0..508
    float acc2[TILE_M][4];
    #pragma unroll
    for (int mi = 0; mi < TILE_M; mi++)
        #pragma unroll
        for (int r = 0; r < 4; r++) acc2[mi][r] = 0.f;

    for (int h = 0; h < Hx; h += 4) {
        float4 pw0 = *reinterpret_cast<const float4*>(pow_ + (size_t)(h+0)*(2*Hx) + j4);
        float4 pw1v = *reinterpret_cast<const float4*>(pow_ + (size_t)(h+1)*(2*Hx) + j4);
        float4 pw2v = *reinterpret_cast<const float4*>(pow_ + (size_t)(h+2)*(2*Hx) + j4);
        float4 pw3 = *reinterpret_cast<const float4*>(pow_ + (size_t)(h+3)*(2*Hx) + j4);
        #pragma unroll
        for (int mi = 0; mi < TILE_M; mi++) {
            float4 uv = *reinterpret_cast<const float4*>(&u_sh[mi][h]);
            acc2[mi][0] = fmaf(uv.x, pw0.x, acc2[mi][0]);
            acc2[mi][1] = fmaf(uv.x, pw0.y, acc2[mi][1]);
            acc2[mi][2] = fmaf(uv.x, pw0.z, acc2[mi][2]);
            acc2[mi][3] = fmaf(uv.x, pw0.w, acc2[mi][3]);
            acc2[mi][0] = fmaf(uv.y, pw1v.x, acc2[mi][0]);
            acc2[mi][1] = fmaf(uv.y, pw1v.y, acc2[mi][1]);
            acc2[mi][2] = fmaf(uv.y, pw1v.z, acc2[mi][2]);
            acc2[mi][3] = fmaf(uv.y, pw1v.w, acc2[mi][3]);
            acc2[mi][0] = fmaf(uv.z, pw2v.x, acc2[mi][0]);
            acc2[mi][1] = fmaf(uv.z, pw2v.y, acc2[mi][1]);
            acc2[mi][2] = fmaf(uv.z, pw2v.z, acc2[mi][2]);
            acc2[mi][3] = fmaf(uv.z, pw2v.w, acc2[mi][3]);
            acc2[mi][0] = fmaf(uv.w, pw3.x, acc2[mi][0]);
            acc2[mi][1] = fmaf(uv.w, pw3.y, acc2[mi][1]);
            acc2[mi][2] = fmaf(uv.w, pw3.z, acc2[mi][2]);
            acc2[mi][3] = fmaf(uv.w, pw3.w, acc2[mi][3]);
        }
    }
    float4 pb4 = *reinterpret_cast<const float4*>(pob + j4);
    #pragma unroll
    for (int mi = 0; mi < TILE_M; mi++) {
        int m = m0 + mi;
        float4 ov;
        ov.x = acc2[mi][0] + pb4.x;
        ov.y = acc2[mi][1] + pb4.y;
        ov.z = acc2[mi][2] + pb4.z;
        ov.w = acc2[mi][3] + pb4.w;
        *reinterpret_cast<float4*>(outO + (size_t)(b*Mx + m)*(2*Hx) + j4) = ov;
    }
}

// ------------------------- launch -------------------------
extern "C" void kernel_launch(void* const* d_in, const int* in_sizes, int n_in,
                              void* d_out, int out_size) {
    (void)in_sizes; (void)n_in; (void)out_size;
    const float* x        = (const float*)d_in[0];
    const float* xdur     = (const float*)d_in[2];
    const int*   xlens    = (const int*)  d_in[3];
    const float* proj_w   = (const float*)d_in[4];
    const float* proj_b   = (const float*)d_in[5];
    const float* conv_w   = (const float*)d_in[6];
    const float* conv_b   = (const float*)d_in[7];
    const float* conv_g   = (const float*)d_in[8];
    const float* conv_bt  = (const float*)d_in[9];
    const float* q_w1     = (const float*)d_in[10];
    const float* q_b1     = (const float*)d_in[11];
    const float* q_g      = (const float*)d_in[12];
    const float* q_bt     = (const float*)d_in[13];
    const float* q_w2     = (const float*)d_in[14];
    const float* q_b2     = (const float*)d_in[15];
    const float* p_w1     = (const float*)d_in[16];
    const float* p_b1     = (const float*)d_in[17];
    const float* p_g      = (const float*)d_in[18];
    const float* p_bt     = (const float*)d_in[19];
    const float* p_w2     = (const float*)d_in[20];
    const float* p_b2     = (const float*)d_in[21];
    const float* proj1_w  = (const float*)d_in[22];
    const float* proj1_b  = (const float*)d_in[23];
    const float* proj2_w  = (const float*)d_in[24];
    const float* proj2_b  = (const float*)d_in[25];
    const float* projo_w  = (const float*)d_in[26];
    const float* projo_b  = (const float*)d_in[27];

    float* out     = (float*)d_out;
    float* outO    = out;                                    // B*M*2H
    float* outMask = out + (size_t)Bx*Mx*2*Hx;               // B*M*T
    float* outLens = outMask + (size_t)Bx*Mx*Tx;             // B
    float* outW    = outLens + Bx;                           // B*Q*M*T

    dim3 ghy(Bx, 4, 5);
    kHY<<<ghy, 128>>>(x, proj_w, proj_b, proj1_w, xlens);
    kConv<<<Bx*Tx, Hx>>>(conv_w, conv_b, conv_g, conv_bt, xlens, xdur, outLens);
    kMain<<<Bx*NTILES, 128>>>(xlens,
        q_w1, q_b1, q_g, q_bt, q_w2, q_b2,
        p_w1, p_b1, p_g, p_bt, p_w2, p_b2,
        proj1_b, proj2_w, proj2_b, projo_w, projo_b,
        outO, outMask, outW);
}